// round 6
// baseline (speedup 1.0000x reference)
#include <cuda_runtime.h>
#include <float.h>

#define VX 64
#define NB 8
#define NP 32
#define PE 32
#define SHARP 100.0f
#define EPSF 1e-8f
#define NTHREADS 256
#define NWARPS 8
#define HPX 32                     // pixels per block (half row)

// Block: one (batch b, row y, x-half). 1024 blocks so the 148-SM chip is fed
// ~7 blocks/SM (occupancy was grid-limited at 512 blocks). 8 warps; lane =
// pixel within the 32-px half; valid polygons are compacted and dealt to
// warps round-robin. Edge precompute is duplicated across the two sibling
// half-blocks (cheap) so no cross-block communication is needed.
__global__ __launch_bounds__(NTHREADS, 6) void extrusion_kernel(
    const float* __restrict__ polygons,   // [B][N][P][2]
    const float* __restrict__ attributes, // [B][4]
    const float* __restrict__ validity,   // [B][N]
    float* __restrict__ out)              // [B][V][V][V]
{
    __shared__ __align__(16) float4 sA[NP * PE];   // x0, exi, syi, cxthr
    __shared__ __align__(16) float4 sB[NP * PE];   // ex, ey, vy, pad
    __shared__ __align__(16) float  sPartial[NWARPS][HPX];
    __shared__ __align__(16) float  sComb[HPX];
    __shared__ int    sIdx[NP];
    __shared__ int    sV;

    const int b    = blockIdx.x >> 7;         // /128
    const int row  = (blockIdx.x >> 1) & 63;
    const int half = blockIdx.x & 1;
    const int tid  = threadIdx.x;
    const float py = (float)row * (1.0f / 63.0f);

    // ---- Phase 1a: validity compaction (warp 0) ----
    if (tid < 32) {
        const bool valid = validity[b * NP + tid] >= 0.5f;
        const unsigned m = __ballot_sync(0xffffffffu, valid);
        if (valid) {
            const int pos = __popc(m & ((1u << tid) - 1u));
            sIdx[pos] = tid;
        }
        if (tid == 0) sV = __popc(m);
    }

    // ---- Phase 1b: per-block edge precompute (py folded in) ----
    const float* poly_b = polygons + (size_t)b * NP * PE * 2;
    #pragma unroll
    for (int i = tid; i < NP * PE; i += NTHREADS) {
        const int n  = i >> 5;
        const int e  = i & 31;
        const int e1 = (e + 1) & 31;
        const float x0 = poly_b[(n * PE + e ) * 2 + 0];
        const float y0 = poly_b[(n * PE + e ) * 2 + 1];
        const float x1 = poly_b[(n * PE + e1) * 2 + 0];
        const float y1 = poly_b[(n * PE + e1) * 2 + 1];
        const float ex = x1 - x0;
        const float ey = y1 - y0;
        const float inv = 1.0f / (ex * ex + ey * ey + EPSF);
        const float vy  = py - y0;
        const float exi = ex * inv;
        const float syi = (vy * ey) * inv;
        const bool ycr = (fminf(y0, y1) <= py) && (fmaxf(y0, y1) > py);
        const float interx = x0 + ex * (vy / (ey + EPSF));
        const float cxthr = ycr ? interx : -FLT_MAX;
        sA[i] = make_float4(x0, exi, syi, cxthr);
        sB[i] = make_float4(ex, ey, vy, 0.0f);
    }
    __syncthreads();

    // ---- Phase 2: SDF + sigmoid + max, 1 pixel per lane ----
    const int lane = tid & 31;
    const int g    = tid >> 5;
    const int xi   = half * HPX + lane;
    const float px = (float)xi * (1.0f / 63.0f);
    const int nv = sV;

    float best = 0.0f;
    #pragma unroll 1
    for (int j = g; j < nv; j += NWARPS) {
        const int n = sIdx[j];
        float min_d2 = FLT_MAX;
        int par = 0;
        const float4* A4 = sA + n * PE;
        const float4* B4 = sB + n * PE;
        #pragma unroll
        for (int e = 0; e < PE; e++) {
            const float4 a = A4[e];       // x0, exi, syi, cxthr
            const float4 c = B4[e];       // ex, ey, vy, -
            const float vx = px - a.x;
            const float t  = __saturatef(fmaf(vx, a.y, a.z));
            const float dx = fmaf(-t, c.x, vx);
            const float dy = fmaf(-t, c.y, c.z);
            min_d2 = fminf(min_d2, fmaf(dy, dy, dx * dx));
            par ^= (a.w > px);
        }
        const float d   = sqrtf(min_d2);
        const float sdf = par ? -d : d;
        best = fmaxf(best, __fdividef(1.0f, 1.0f + __expf(SHARP * sdf)));
    }
    sPartial[g][lane] = best;
    __syncthreads();

    // ---- Phase 3: 8-way max reduce -> combined half-row ----
    if (tid < HPX) {
        float m = sPartial[0][tid];
        #pragma unroll
        for (int w = 1; w < NWARPS; w++) m = fmaxf(m, sPartial[w][tid]);
        sComb[tid] = m;
    }
    __syncthreads();

    // ---- Phase 4: expand along z, coalesced float4 stores ----
    int h = (int)floorf(attributes[b * 4 + 0] * (float)VX);
    h = max(1, min(VX, h));

    const float4* comb4 = (const float4*)sComb;            // 8 float4
    float* out_base = out + (size_t)b * VX * VX * VX
                          + (size_t)row * VX + half * HPX;
    const float4 zero4 = make_float4(0.f, 0.f, 0.f, 0.f);
    #pragma unroll
    for (int i = tid; i < VX * 8; i += NTHREADS) {          // 2 iterations
        const int z = i >> 3;
        const int q = i & 7;
        float4* dst = (float4*)(out_base + (size_t)z * VX * VX);
        dst[q] = (z < h) ? comb4[q] : zero4;
    }
}

extern "C" void kernel_launch(void* const* d_in, const int* in_sizes, int n_in,
                              void* d_out, int out_size) {
    const float* polygons   = (const float*)d_in[0];
    const float* attributes = (const float*)d_in[1];
    const float* validity   = (const float*)d_in[2];
    float* out = (float*)d_out;
    (void)in_sizes; (void)n_in; (void)out_size;

    extrusion_kernel<<<NB * VX * 2, NTHREADS>>>(polygons, attributes, validity, out);
}

// round 7
// speedup vs baseline: 1.0057x; 1.0057x over previous
#include <cuda_runtime.h>
#include <float.h>

#define VX 64
#define NB 8
#define NP 32
#define PE 32
#define SHARP 100.0f
#define EPSF 1e-8f
#define NTHREADS 256
#define NWARPS 8
#define NPG 16                       // polygons per block (half of NP)

__device__ __forceinline__ unsigned smem_u32(const void* p) {
    unsigned a;
    asm("{ .reg .u64 t; cvta.to.shared.u64 t, %1; cvt.u32.u64 %0, t; }"
        : "=r"(a) : "l"(p));
    return a;
}
__device__ __forceinline__ float dsmem_read_f32(unsigned local_addr, unsigned peer_rank) {
    unsigned rem; float v;
    asm("mapa.shared::cluster.u32 %0, %1, %2;" : "=r"(rem) : "r"(local_addr), "r"(peer_rank));
    asm volatile("ld.shared::cluster.f32 %0, [%1];" : "=f"(v) : "r"(rem));
    return v;
}
__device__ __forceinline__ void cluster_sync_all() {
    asm volatile("barrier.cluster.arrive.aligned;" ::: "memory");
    asm volatile("barrier.cluster.wait.aligned;"   ::: "memory");
}

// Cluster of 2 CTAs per (batch, row): rank r handles polygons {r, r+2, ..., r+30}.
// Each CTA computes its partial combined row (2 px/lane, compacted valid polys
// dealt round-robin to 8 warps), siblings merge via DSMEM, and each CTA writes
// half of the z-slabs. Grid order: (rank, b, row) low-to-high so SMs mix batches.
__global__ __launch_bounds__(NTHREADS, 4) __cluster_dims__(2, 1, 1)
void extrusion_kernel(
    const float* __restrict__ polygons,   // [B][N][P][2]
    const float* __restrict__ attributes, // [B][4]
    const float* __restrict__ validity,   // [B][N]
    float* __restrict__ out)              // [B][V][V][V]
{
    __shared__ __align__(16) float4 sA[NPG * PE];   // x0, exi, syi, cxthr
    __shared__ __align__(16) float4 sB[NPG * PE];   // ex, ey, vy, pad
    __shared__ __align__(16) float  sPartial[NWARPS][VX];
    __shared__ __align__(16) float  sComb[VX];      // own partial (peer reads this)
    __shared__ __align__(16) float  sFinal[VX];     // after peer merge
    __shared__ int sIdx[NPG];
    __shared__ int sV;

    const int bid  = blockIdx.x;
    const int rank = bid & 1;                 // == cluster cta rank
    const int b    = (bid >> 1) & 7;
    const int row  = bid >> 4;
    const int tid  = threadIdx.x;
    const float py = (float)row * (1.0f / 63.0f);

    // ---- Phase 1a: validity compaction over this CTA's 16 strided polys ----
    if (tid < NPG) {
        const int n = rank + 2 * tid;
        const bool valid = validity[b * NP + n] >= 0.5f;
        const unsigned m = __ballot_sync(0x0000ffffu, valid);
        if (valid) {
            const int pos = __popc(m & ((1u << tid) - 1u));
            sIdx[pos] = tid;                  // local poly index 0..15
        }
        if (tid == 0) sV = __popc(m);
    }

    // ---- Phase 1b: edge precompute, 16 polys x 32 edges (py folded in) ----
    const float* poly_b = polygons + (size_t)b * NP * PE * 2;
    #pragma unroll
    for (int i = tid; i < NPG * PE; i += NTHREADS) {   // 2 iterations
        const int li = i >> 5;                // local poly
        const int n  = rank + 2 * li;         // global poly
        const int e  = i & 31;
        const int e1 = (e + 1) & 31;
        const float x0 = poly_b[(n * PE + e ) * 2 + 0];
        const float y0 = poly_b[(n * PE + e ) * 2 + 1];
        const float x1 = poly_b[(n * PE + e1) * 2 + 0];
        const float y1 = poly_b[(n * PE + e1) * 2 + 1];
        const float ex = x1 - x0;
        const float ey = y1 - y0;
        const float inv = 1.0f / (ex * ex + ey * ey + EPSF);
        const float vy  = py - y0;
        const float exi = ex * inv;
        const float syi = (vy * ey) * inv;
        const bool ycr = (fminf(y0, y1) <= py) && (fmaxf(y0, y1) > py);
        const float interx = x0 + ex * (vy / (ey + EPSF));
        const float cxthr = ycr ? interx : -FLT_MAX;
        sA[i] = make_float4(x0, exi, syi, cxthr);
        sB[i] = make_float4(ex, ey, vy, 0.0f);
    }
    __syncthreads();

    // ---- Phase 2: SDF + sigmoid + max, 2 pixels per lane ----
    const int lane = tid & 31;
    const int g    = tid >> 5;
    const float pxa = (float)lane        * (1.0f / 63.0f);
    const float pxb = (float)(lane + 32) * (1.0f / 63.0f);
    const int nv = sV;

    float best_a = 0.0f, best_b = 0.0f;
    #pragma unroll 1
    for (int j = g; j < nv; j += NWARPS) {     // typically one iteration
        const int li = sIdx[j];
        float min_a = FLT_MAX, min_b = FLT_MAX;
        int par_a = 0, par_b = 0;
        const float4* A4 = sA + li * PE;
        const float4* B4 = sB + li * PE;
        #pragma unroll
        for (int e = 0; e < PE; e++) {
            const float4 a = A4[e];
            const float4 c = B4[e];
            const float vxa = pxa - a.x;
            const float vxb = pxb - a.x;
            const float ta = __saturatef(fmaf(vxa, a.y, a.z));
            const float tb = __saturatef(fmaf(vxb, a.y, a.z));
            const float dxa = fmaf(-ta, c.x, vxa);
            const float dxb = fmaf(-tb, c.x, vxb);
            const float dya = fmaf(-ta, c.y, c.z);
            const float dyb = fmaf(-tb, c.y, c.z);
            min_a = fminf(min_a, fmaf(dya, dya, dxa * dxa));
            min_b = fminf(min_b, fmaf(dyb, dyb, dxb * dxb));
            par_a ^= (a.w > pxa);
            par_b ^= (a.w > pxb);
        }
        const float da = sqrtf(min_a);
        const float db = sqrtf(min_b);
        const float sa = par_a ? -da : da;
        const float sb = par_b ? -db : db;
        best_a = fmaxf(best_a, __fdividef(1.0f, 1.0f + __expf(SHARP * sa)));
        best_b = fmaxf(best_b, __fdividef(1.0f, 1.0f + __expf(SHARP * sb)));
    }
    sPartial[g][lane]      = best_a;
    sPartial[g][lane + 32] = best_b;
    __syncthreads();

    // ---- Phase 3: local 8-way reduce into sComb ----
    if (tid < VX) {
        float m = sPartial[0][tid];
        #pragma unroll
        for (int w = 1; w < NWARPS; w++) m = fmaxf(m, sPartial[w][tid]);
        sComb[tid] = m;
    }
    __syncthreads();

    // ---- Phase 3b: cluster merge via DSMEM ----
    cluster_sync_all();                        // my sComb visible to peer & vice versa
    if (tid < VX) {
        const unsigned my_addr = smem_u32(&sComb[tid]);
        const float peer = dsmem_read_f32(my_addr, 1u - (unsigned)rank);
        sFinal[tid] = fmaxf(sComb[tid], peer);
    }
    __syncthreads();
    cluster_sync_all();                        // peer done reading my sComb; safe to proceed/exit

    // ---- Phase 4: this CTA writes z in [rank*32, rank*32+32) ----
    int h = (int)floorf(attributes[b * 4 + 0] * (float)VX);
    h = max(1, min(VX, h));

    const float4* comb4 = (const float4*)sFinal;   // 16 float4
    float* out_base = out + (size_t)b * VX * VX * VX + (size_t)row * VX;
    const float4 zero4 = make_float4(0.f, 0.f, 0.f, 0.f);
    #pragma unroll
    for (int i = tid; i < 32 * 16; i += NTHREADS) {    // 2 iterations
        const int z = rank * 32 + (i >> 4);
        const int q = i & 15;
        float4* dst = (float4*)(out_base + (size_t)z * VX * VX);
        dst[q] = (z < h) ? comb4[q] : zero4;
    }
}

extern "C" void kernel_launch(void* const* d_in, const int* in_sizes, int n_in,
                              void* d_out, int out_size) {
    const float* polygons   = (const float*)d_in[0];
    const float* attributes = (const float*)d_in[1];
    const float* validity   = (const float*)d_in[2];
    float* out = (float*)d_out;
    (void)in_sizes; (void)n_in; (void)out_size;

    extrusion_kernel<<<NB * VX * 2, NTHREADS>>>(polygons, attributes, validity, out);
}

// round 9
// speedup vs baseline: 1.1234x; 1.1170x over previous
#include <cuda_runtime.h>
#include <float.h>

#define VX 64
#define NB 8
#define NP 32
#define PE 32
#define SHARP 100.0f
#define EPSF 1e-8f
#define NTHREADS 256
#define NWARPS 8

__device__ __forceinline__ float ex2_approx(float x) {
    float r; asm("ex2.approx.ftz.f32 %0, %1;" : "=f"(r) : "f"(x)); return r;
}
__device__ __forceinline__ float rcp_approx(float x) {
    float r; asm("rcp.approx.ftz.f32 %0, %1;" : "=f"(r) : "f"(x)); return r;
}

// Block: one (batch b, row y). 8 warps, 2 pixels per lane.
// Phase 1 precomputes, per edge: distance data (24B) AND folds the whole
// crossing/parity computation into a per-polygon 64-bit pixel mask
// (monotone threshold -> prefix mask, XOR-reduced across edges), so the
// 32-edge inner loop has NO predicate work at all: 16 issue slots / 2 pixels.
// Zero z-slabs (z >= h) are stored up front, overlapping STG with compute.
__global__ __launch_bounds__(NTHREADS, 4) void extrusion_kernel(
    const float* __restrict__ polygons,   // [B][N][P][2]
    const float* __restrict__ attributes, // [B][4]
    const float* __restrict__ validity,   // [B][N]
    float* __restrict__ out)              // [B][V][V][V]
{
    __shared__ __align__(16) float4 sA[NP * PE];   // x0, exi, syi, ey
    __shared__ __align__(16) float2 sC[NP * PE];   // ex, vy
    __shared__ __align__(16) float  sPartial[NWARPS][VX];
    __shared__ __align__(16) float  sComb[VX];
    __shared__ unsigned sParLo[NP], sParHi[NP];    // per-poly parity bitmask
    __shared__ int sIdx[NP];
    __shared__ int sV;

    const int b   = blockIdx.x >> 6;
    const int row = blockIdx.x & 63;
    const int tid = threadIdx.x;
    const float py = (float)row * (1.0f / 63.0f);

    // ---- Phase 0: h + early zero stores (independent of SDF) ----
    int h = (int)floorf(attributes[b * 4 + 0] * (float)VX);
    h = max(1, min(VX, h));
    float* out_base = out + (size_t)b * VX * VX * VX + (size_t)row * VX;
    const float4 zero4 = make_float4(0.f, 0.f, 0.f, 0.f);
    for (int i = h * 16 + tid; i < VX * 16; i += NTHREADS) {
        const int z = i >> 4;
        const int q = i & 15;
        ((float4*)(out_base + (size_t)z * VX * VX))[q] = zero4;
    }

    // ---- Phase 1a: validity compaction (warp 0) ----
    if (tid < 32) {
        const bool valid = validity[b * NP + tid] >= 0.5f;
        const unsigned m = __ballot_sync(0xffffffffu, valid);
        if (valid) {
            const int pos = __popc(m & ((1u << tid) - 1u));
            sIdx[pos] = tid;
        }
        if (tid == 0) sV = __popc(m);
    }

    // ---- Phase 1b: edge precompute + per-poly parity masks ----
    // warp w, lane e handles edge e of polys {w, w+8, w+16, w+24}.
    const float2* pv = (const float2*)(polygons + (size_t)b * NP * PE * 2);
    {
        const int w = tid >> 5;
        const int e = tid & 31;
        const int e1 = (e + 1) & 31;
        #pragma unroll
        for (int k = 0; k < 4; k++) {
            const int n = w + 8 * k;
            const float2 v0 = pv[n * PE + e];
            const float2 v1 = pv[n * PE + e1];
            const float ex = v1.x - v0.x;
            const float ey = v1.y - v0.y;
            const float inv = 1.0f / (ex * ex + ey * ey + EPSF);
            const float vy  = py - v0.y;
            sA[n * PE + e] = make_float4(v0.x, ex * inv, (vy * ey) * inv, ey);
            sC[n * PE + e] = make_float2(ex, vy);
            // crossing threshold -> prefix bitmask over the 64 pixel columns
            const bool ycr = (fminf(v0.y, v1.y) <= py) && (fmaxf(v0.y, v1.y) > py);
            const float interx = v0.x + ex * (vy / (ey + EPSF));
            const float cxthr = ycr ? interx : -FLT_MAX;
            float t = fminf(fmaxf(cxthr * 63.0f, -1.0f), 65.0f);
            int idx = (int)ceilf(t);
            idx = max(0, min(64, idx));
            const unsigned long long m64 =
                (idx >= 64) ? ~0ull : ((1ull << idx) - 1ull);
            const unsigned lo = __reduce_xor_sync(0xffffffffu, (unsigned)m64);
            const unsigned hi = __reduce_xor_sync(0xffffffffu, (unsigned)(m64 >> 32));
            if (e == 0) { sParLo[n] = lo; sParHi[n] = hi; }
        }
    }
    __syncthreads();

    // ---- Phase 2: SDF + sigmoid + max, 2 pixels per lane, zero predicate work ----
    const int lane = tid & 31;
    const int g    = tid >> 5;
    const float pxa = (float)lane        * (1.0f / 63.0f);
    const float pxb = (float)(lane + 32) * (1.0f / 63.0f);
    const int nv = sV;

    float best_a = 0.0f, best_b = 0.0f;
    #pragma unroll 1
    for (int j = g; j < nv; j += NWARPS) {
        const int n = sIdx[j];
        const unsigned sign_a = ((sParLo[n] >> lane) & 1u) << 31;
        const unsigned sign_b = ((sParHi[n] >> lane) & 1u) << 31;
        float min_a = FLT_MAX, min_b = FLT_MAX;
        const float4* A4 = sA + n * PE;
        const float2* C2 = sC + n * PE;
        #pragma unroll
        for (int e = 0; e < PE; e++) {
            const float4 a = A4[e];       // x0, exi, syi, ey
            const float2 c = C2[e];       // ex, vy
            const float vxa = pxa - a.x;
            const float vxb = pxb - a.x;
            const float ta = __saturatef(fmaf(vxa, a.y, a.z));
            const float tb = __saturatef(fmaf(vxb, a.y, a.z));
            const float dxa = fmaf(-ta, c.x, vxa);
            const float dxb = fmaf(-tb, c.x, vxb);
            const float dya = fmaf(-ta, a.w, c.y);
            const float dyb = fmaf(-tb, a.w, c.y);
            min_a = fminf(min_a, fmaf(dya, dya, dxa * dxa));
            min_b = fminf(min_b, fmaf(dyb, dyb, dxb * dxb));
        }
        // signed distance via bit-XOR; sigmoid(-100*sdf) = 1/(1 + 2^(144.27*sdf))
        const float sa = __uint_as_float(__float_as_uint(sqrtf(min_a)) ^ sign_a);
        const float sb = __uint_as_float(__float_as_uint(sqrtf(min_b)) ^ sign_b);
        best_a = fmaxf(best_a, rcp_approx(1.0f + ex2_approx(sa * 144.269504f)));
        best_b = fmaxf(best_b, rcp_approx(1.0f + ex2_approx(sb * 144.269504f)));
    }
    sPartial[g][lane]      = best_a;
    sPartial[g][lane + 32] = best_b;
    __syncthreads();

    // ---- Phase 3: 8-way max reduce -> combined row ----
    if (tid < VX) {
        float m = sPartial[0][tid];
        #pragma unroll
        for (int w = 1; w < NWARPS; w++) m = fmaxf(m, sPartial[w][tid]);
        sComb[tid] = m;
    }
    __syncthreads();

    // ---- Phase 4: store the z < h slabs ----
    const float4* comb4 = (const float4*)sComb;
    for (int i = tid; i < h * 16; i += NTHREADS) {
        const int z = i >> 4;
        const int q = i & 15;
        ((float4*)(out_base + (size_t)z * VX * VX))[q] = comb4[q];
    }
}

extern "C" void kernel_launch(void* const* d_in, const int* in_sizes, int n_in,
                              void* d_out, int out_size) {
    const float* polygons   = (const float*)d_in[0];
    const float* attributes = (const float*)d_in[1];
    const float* validity   = (const float*)d_in[2];
    float* out = (float*)d_out;
    (void)in_sizes; (void)n_in; (void)out_size;

    extrusion_kernel<<<NB * VX, NTHREADS>>>(polygons, attributes, validity, out);
}